// round 3
// baseline (speedup 1.0000x reference)
#include <cuda_runtime.h>
#include <cstdint>

// Problem constants
#define BN 32768
#define DN 256
#define KN 2048

// GEMM tiling
#define TM 128
#define TN 128
#define TK 32

#define SMEM_FLOATS (DN*TM + TK*TN + TN)   // 32768 + 4096 + 128 = 36992
#define SMEM_BYTES  (SMEM_FLOATS * 4)      // 147968 bytes

// Output layout (fp32, concatenated in reference return order):
//   [0, BN*DN)             quantized_st
//   [BN*DN]                vq_loss
//   [BN*DN+1]              entropy_vq
//   [BN*DN+2, +BN)         encoding_inds (cast to float)
//   [BN*DN+2+BN]           cluster_metric
#define Q_OFF    0
#define TAIL_OFF (BN*DN)
#define IND_OFF  (BN*DN + 2)

// Scratch (device globals; no allocation allowed)
__device__ float g_rowA[BN];     // sum(latents^2) per row
__device__ float g_rowB[KN];     // sum(embedding^2) per code
__device__ float g_minval[BN];   // min dist per row (quantized like reference)
__device__ int   g_minidx[BN];   // argmin index per row
__device__ int   g_counts[KN];   // histogram
__device__ float g_sqsum;        // sum (q - l)^2
__device__ float g_mindsum;      // sum of min dists

// ---------------------------------------------------------------------------
__global__ void vq_init()
{
    int t = blockIdx.x * blockDim.x + threadIdx.x;
    if (t < KN) g_counts[t] = 0;
    if (t == 0) { g_sqsum = 0.f; g_mindsum = 0.f; }
}

// Row sum of squares: one warp per row. Per-lane sequential over strided
// elements (lane + 32*j, coalesced), then shfl-down tree — mirrors a typical
// XLA GPU row-reduction order (tie-sensitivity lives in this value for A).
__global__ void vq_rowsumsq(const float* __restrict__ x, int nrows, int which)
{
    int gw   = (blockIdx.x * blockDim.x + threadIdx.x) >> 5;
    int lane = threadIdx.x & 31;
    if (gw >= nrows) return;
    const float* row = x + (size_t)gw * DN;
    float s = 0.f;
    #pragma unroll
    for (int j = 0; j < DN / 32; j++) {
        float v = row[lane + 32 * j];
        s = __fadd_rn(s, __fmul_rn(v, v));   // square then add (no fma contraction)
    }
    #pragma unroll
    for (int off = 16; off > 0; off >>= 1)
        s = __fadd_rn(s, __shfl_down_sync(0xffffffffu, s, off));
    if (lane == 0) {
        if (which) g_rowB[gw] = s; else g_rowA[gw] = s;
    }
}

// ---------------------------------------------------------------------------
// Fused GEMM + argmin. One block = 128 latent rows vs ALL 2048 codes.
// Latents tile lives in smem (transposed, [d][row]) across all 16 code tiles.
// dist is computed with the reference's exact fp32 rounding structure:
//   d = fl( fl(A_row + B_k) - fl(2 * dot) )
// argmin uses lowest-index tie-break (jnp.argmin first-occurrence semantics).
__global__ __launch_bounds__(256, 1)
void vq_gemm_argmin(const float* __restrict__ lat, const float* __restrict__ emb)
{
    extern __shared__ float sm[];
    float* lat_s = sm;                     // [DN][TM]
    float* emb_s = sm + DN * TM;           // [TK][TN]  (reused as reduction area)
    float* b2_s  = sm + DN * TM + TK * TN; // [TN]

    int tid  = threadIdx.x;
    int tx   = tid & 15;      // column group (8 codes)
    int ty   = tid >> 4;      // row group (8 rows)
    int row0 = blockIdx.x * TM;

    // Load latents tile, store transposed lat_s[d][r]
    for (int i = tid; i < TM * DN / 4; i += 256) {
        int r  = i >> 6;       // / (DN/4)
        int c4 = i & 63;
        float4 v = *reinterpret_cast<const float4*>(lat + (size_t)(row0 + r) * DN + c4 * 4);
        lat_s[(c4 * 4 + 0) * TM + r] = v.x;
        lat_s[(c4 * 4 + 1) * TM + r] = v.y;
        lat_s[(c4 * 4 + 2) * TM + r] = v.z;
        lat_s[(c4 * 4 + 3) * TM + r] = v.w;
    }

    float Areg[8];
    #pragma unroll
    for (int i = 0; i < 8; i++) Areg[i] = g_rowA[row0 + ty * 8 + i];

    float minv[8]; int mini[8];
    #pragma unroll
    for (int i = 0; i < 8; i++) { minv[i] = __int_as_float(0x7f800000); mini[i] = 0; }

    for (int nt = 0; nt < KN / TN; nt++) {
        int kc0 = nt * TN;
        __syncthreads();                 // protect b2_s/emb_s reuse from prior iter
        if (tid < TN) b2_s[tid] = g_rowB[kc0 + tid];

        float acc[8][8];
        #pragma unroll
        for (int i = 0; i < 8; i++)
            #pragma unroll
            for (int j = 0; j < 8; j++) acc[i][j] = 0.f;

        for (int kc = 0; kc < DN; kc += TK) {
            __syncthreads();
            // Load embedding chunk transposed: emb_s[dd][code]
            for (int i = tid; i < TN * TK / 4; i += 256) {
                int c  = i >> 3;
                int d4 = i & 7;
                float4 v = *reinterpret_cast<const float4*>(
                    emb + (size_t)(kc0 + c) * DN + kc + d4 * 4);
                emb_s[(d4 * 4 + 0) * TN + c] = v.x;
                emb_s[(d4 * 4 + 1) * TN + c] = v.y;
                emb_s[(d4 * 4 + 2) * TN + c] = v.z;
                emb_s[(d4 * 4 + 3) * TN + c] = v.w;
            }
            __syncthreads();
            #pragma unroll 4
            for (int kk = 0; kk < TK; kk++) {
                const float* ap = lat_s + (kc + kk) * TM + ty * 8;
                const float* bp = emb_s + kk * TN + tx * 8;
                float4 a0 = *reinterpret_cast<const float4*>(ap);
                float4 a1 = *reinterpret_cast<const float4*>(ap + 4);
                float4 b0 = *reinterpret_cast<const float4*>(bp);
                float4 b1 = *reinterpret_cast<const float4*>(bp + 4);
                float a[8] = {a0.x, a0.y, a0.z, a0.w, a1.x, a1.y, a1.z, a1.w};
                float b[8] = {b0.x, b0.y, b0.z, b0.w, b1.x, b1.y, b1.z, b1.w};
                #pragma unroll
                for (int i = 0; i < 8; i++)
                    #pragma unroll
                    for (int j = 0; j < 8; j++)
                        acc[i][j] = __fmaf_rn(a[i], b[j], acc[i][j]);
            }
        }

        // Epilogue: reference-faithful dist + running argmin (k ascending per row)
        #pragma unroll
        for (int j = 0; j < 8; j++) {
            int   k  = kc0 + tx * 8 + j;
            float b2 = b2_s[tx * 8 + j];
            #pragma unroll
            for (int i = 0; i < 8; i++) {
                float d = __fsub_rn(__fadd_rn(Areg[i], b2), __fmul_rn(2.0f, acc[i][j]));
                if (d < minv[i]) { minv[i] = d; mini[i] = k; }  // strict < keeps lowest k
            }
        }
    }

    // Cross-thread reduction over the 16 column-group threads per row
    __syncthreads();
    float* redv = emb_s;                        // [TM][16]
    int*   redi = (int*)(emb_s + TM * 16);      // [TM][16]
    #pragma unroll
    for (int i = 0; i < 8; i++) {
        int r = ty * 8 + i;
        redv[r * 16 + tx] = minv[i];
        redi[r * 16 + tx] = mini[i];
    }
    __syncthreads();
    if (tid < TM) {
        float bv = redv[tid * 16];
        int   bi = redi[tid * 16];
        #pragma unroll
        for (int t = 1; t < 16; t++) {
            float v  = redv[tid * 16 + t];
            int   ii = redi[tid * 16 + t];
            if (v < bv || (v == bv && ii < bi)) { bv = v; bi = ii; }
        }
        g_minval[row0 + tid] = bv;
        g_minidx[row0 + tid] = bi;
    }
}

// ---------------------------------------------------------------------------
__global__ void vq_hist(float* __restrict__ out_inds)
{
    __shared__ float s[256];
    int b = blockIdx.x * blockDim.x + threadIdx.x;
    float v = 0.f;
    if (b < BN) {
        int idx = g_minidx[b];
        out_inds[b] = (float)idx;
        atomicAdd(&g_counts[idx], 1);
        v = g_minval[b];
    }
    s[threadIdx.x] = v;
    __syncthreads();
    for (int o = 128; o > 0; o >>= 1) {
        if (threadIdx.x < o) s[threadIdx.x] += s[threadIdx.x + o];
        __syncthreads();
    }
    if (threadIdx.x == 0) atomicAdd(&g_mindsum, s[0]);
}

// Gather + straight-through output + squared-error sum.
// quantized_st replicated exactly as reference: fl(l + fl(q - l))
__global__ void vq_gather(const float* __restrict__ lat, const float* __restrict__ emb,
                          float* __restrict__ outq)
{
    __shared__ float s[256];
    int i4 = blockIdx.x * blockDim.x + threadIdx.x;
    float ls = 0.f;
    if (i4 < BN * DN / 4) {
        int b   = i4 >> 6;   // / (DN/4)
        int idx = g_minidx[b];
        float4 l = reinterpret_cast<const float4*>(lat)[i4];
        float4 q = reinterpret_cast<const float4*>(emb)[(size_t)idx * (DN / 4) + (i4 & 63)];
        float4 o; float d;
        d = __fsub_rn(q.x, l.x); o.x = __fadd_rn(l.x, d); ls = __fmaf_rn(d, d, ls);
        d = __fsub_rn(q.y, l.y); o.y = __fadd_rn(l.y, d); ls = __fmaf_rn(d, d, ls);
        d = __fsub_rn(q.z, l.z); o.z = __fadd_rn(l.z, d); ls = __fmaf_rn(d, d, ls);
        d = __fsub_rn(q.w, l.w); o.w = __fadd_rn(l.w, d); ls = __fmaf_rn(d, d, ls);
        reinterpret_cast<float4*>(outq)[i4] = o;
    }
    s[threadIdx.x] = ls;
    __syncthreads();
    for (int o2 = 128; o2 > 0; o2 >>= 1) {
        if (threadIdx.x < o2) s[threadIdx.x] += s[threadIdx.x + o2];
        __syncthreads();
    }
    if (threadIdx.x == 0) atomicAdd(&g_sqsum, s[0]);
}

__global__ void vq_finalize(float* __restrict__ out_tail)
{
    __shared__ float s[256];
    float loc = 0.f;
    for (int k = threadIdx.x; k < KN; k += 256) {
        float p = (float)g_counts[k] * (1.0f / BN);
        loc += p * logf(p + 1e-10f);
    }
    s[threadIdx.x] = loc;
    __syncthreads();
    for (int o = 128; o > 0; o >>= 1) {
        if (threadIdx.x < o) s[threadIdx.x] += s[threadIdx.x + o];
        __syncthreads();
    }
    if (threadIdx.x == 0) {
        float mse = g_sqsum * (1.0f / (float)(BN * (size_t)DN));  // 2^-23 exact
        out_tail[0] = __fadd_rn(__fmul_rn(mse, 0.25f), mse);      // beta*c + e
        out_tail[1] = -s[0];                                       // entropy
        out_tail[2 + BN] = g_mindsum * (1.0f / BN);                // cluster metric
    }
}

// ---------------------------------------------------------------------------
extern "C" void kernel_launch(void* const* d_in, const int* in_sizes, int n_in,
                              void* d_out, int out_size)
{
    (void)in_sizes; (void)n_in; (void)out_size;
    const float* lat = (const float*)d_in[0];   // [BN, DN] fp32
    const float* emb = (const float*)d_in[1];   // [KN, DN] fp32
    float* out = (float*)d_out;

    cudaFuncSetAttribute(vq_gemm_argmin,
                         cudaFuncAttributeMaxDynamicSharedMemorySize, SMEM_BYTES);

    vq_init<<<(KN + 255) / 256, 256>>>();
    vq_rowsumsq<<<(BN * 32) / 256, 256>>>(lat, BN, 0);
    vq_rowsumsq<<<(KN * 32) / 256, 256>>>(emb, KN, 1);
    vq_gemm_argmin<<<BN / TM, 256, SMEM_BYTES>>>(lat, emb);
    vq_hist<<<BN / 256, 256>>>(out + IND_OFF);
    vq_gather<<<(BN * DN / 4) / 256, 256>>>(lat, emb, out + Q_OFF);
    vq_finalize<<<1, 256>>>(out + TAIL_OFF);
}

// round 4
// speedup vs baseline: 1.0134x; 1.0134x over previous
#include <cuda_runtime.h>
#include <cstdint>

// Problem constants
#define BN 32768
#define DN 256
#define KN 2048

// GEMM tiling
#define TM 128
#define TN 128
#define TK 32

#define SMEM_FLOATS (DN*TM + TK*TN + TN)   // 32768 + 4096 + 128 = 36992
#define SMEM_BYTES  (SMEM_FLOATS * 4)      // 147968 bytes

// Output layout (fp32, concatenated in reference return order):
//   [0, BN*DN)             quantized_st
//   [BN*DN]                vq_loss
//   [BN*DN+1]              entropy_vq
//   [BN*DN+2, +BN)         encoding_inds (cast to float)
//   [BN*DN+2+BN]           cluster_metric
#define Q_OFF    0
#define TAIL_OFF (BN*DN)
#define IND_OFF  (BN*DN + 2)

// Scratch (device globals; no allocation allowed)
__device__ float g_rowA[BN];     // sum(latents^2) per row
__device__ float g_rowB[KN];     // sum(embedding^2) per code
__device__ float g_minval[BN];   // min dist per row (quantized like reference)
__device__ int   g_minidx[BN];   // argmin index per row
__device__ int   g_counts[KN];   // histogram
__device__ float g_sqsum;        // sum (q - l)^2
__device__ float g_mindsum;      // sum of min dists

// ---------------------------------------------------------------------------
// Packed fp32x2 FMA helpers. fma.rn.f32x2 rounds each 32-bit lane exactly like
// scalar FFMA -> bit-identical accumulation per component.
__device__ __forceinline__ void ffma2(unsigned long long& d,
                                      unsigned long long a,
                                      unsigned long long b)
{
    asm("fma.rn.f32x2 %0, %1, %2, %0;" : "+l"(d) : "l"(a), "l"(b));
}
__device__ __forceinline__ unsigned long long dup2(float v)
{
    unsigned long long r;
    unsigned int u = __float_as_uint(v);
    asm("mov.b64 %0, {%1, %1};" : "=l"(r) : "r"(u));
    return r;
}
__device__ __forceinline__ void unpack2(unsigned long long v, float& lo, float& hi)
{
    unsigned int a, b;
    asm("mov.b64 {%0, %1}, %2;" : "=r"(a), "=r"(b) : "l"(v));
    lo = __uint_as_float(a);
    hi = __uint_as_float(b);
}

// ---------------------------------------------------------------------------
__global__ void vq_init()
{
    int t = blockIdx.x * blockDim.x + threadIdx.x;
    if (t < KN) g_counts[t] = 0;
    if (t == 0) { g_sqsum = 0.f; g_mindsum = 0.f; }
}

// Row sum of squares: one warp per row (coalesced strided read + shfl tree).
__global__ void vq_rowsumsq(const float* __restrict__ x, int nrows, int which)
{
    int gw   = (blockIdx.x * blockDim.x + threadIdx.x) >> 5;
    int lane = threadIdx.x & 31;
    if (gw >= nrows) return;
    const float* row = x + (size_t)gw * DN;
    float s = 0.f;
    #pragma unroll
    for (int j = 0; j < DN / 32; j++) {
        float v = row[lane + 32 * j];
        s = __fadd_rn(s, __fmul_rn(v, v));   // square then add (no fma contraction)
    }
    #pragma unroll
    for (int off = 16; off > 0; off >>= 1)
        s = __fadd_rn(s, __shfl_down_sync(0xffffffffu, s, off));
    if (lane == 0) {
        if (which) g_rowB[gw] = s; else g_rowA[gw] = s;
    }
}

// ---------------------------------------------------------------------------
// Fused GEMM + argmin, packed-f32x2 mainloop.
// One block = 128 latent rows vs ALL 2048 codes; latents tile resident in smem.
// dist keeps the reference rounding structure:
//   d = fl( fl(A_row + B_k) - fl(2 * dot) ),  dot = sequential fma over d=0..255
// argmin = lowest-index tie-break.
__global__ __launch_bounds__(256, 1)
void vq_gemm_argmin(const float* __restrict__ lat, const float* __restrict__ emb)
{
    extern __shared__ float sm[];
    float* lat_s = sm;                     // [DN][TM]  (rows adjacent -> free f32x2 pairs)
    float* emb_s = sm + DN * TM;           // [TK][TN]  (reused as reduction area)
    float* b2_s  = sm + DN * TM + TK * TN; // [TN]

    int tid  = threadIdx.x;
    int tx   = tid & 15;      // column group (8 codes)
    int ty   = tid >> 4;      // row group (8 rows = 4 packed pairs)
    int row0 = blockIdx.x * TM;

    // Load latents tile, store transposed lat_s[d][r]
    for (int i = tid; i < TM * DN / 4; i += 256) {
        int r  = i >> 6;       // / (DN/4)
        int c4 = i & 63;
        float4 v = *reinterpret_cast<const float4*>(lat + (size_t)(row0 + r) * DN + c4 * 4);
        lat_s[(c4 * 4 + 0) * TM + r] = v.x;
        lat_s[(c4 * 4 + 1) * TM + r] = v.y;
        lat_s[(c4 * 4 + 2) * TM + r] = v.z;
        lat_s[(c4 * 4 + 3) * TM + r] = v.w;
    }

    float Areg[8];
    #pragma unroll
    for (int i = 0; i < 8; i++) Areg[i] = g_rowA[row0 + ty * 8 + i];

    float minv[8]; int mini[8];
    #pragma unroll
    for (int i = 0; i < 8; i++) { minv[i] = __int_as_float(0x7f800000); mini[i] = 0; }

    for (int nt = 0; nt < KN / TN; nt++) {
        int kc0 = nt * TN;
        __syncthreads();                 // protect b2_s/emb_s reuse from prior iter
        if (tid < TN) b2_s[tid] = g_rowB[kc0 + tid];

        // acc2[i2][j]: packed pair of rows (ty*8 + 2*i2, ty*8 + 2*i2 + 1), code j
        unsigned long long acc2[4][8];
        #pragma unroll
        for (int i = 0; i < 4; i++)
            #pragma unroll
            for (int j = 0; j < 8; j++) acc2[i][j] = 0ull;

        for (int kc = 0; kc < DN; kc += TK) {
            __syncthreads();
            // Load embedding chunk transposed: emb_s[dd][code]
            for (int i = tid; i < TN * TK / 4; i += 256) {
                int c  = i >> 3;
                int d4 = i & 7;
                float4 v = *reinterpret_cast<const float4*>(
                    emb + (size_t)(kc0 + c) * DN + kc + d4 * 4);
                emb_s[(d4 * 4 + 0) * TN + c] = v.x;
                emb_s[(d4 * 4 + 1) * TN + c] = v.y;
                emb_s[(d4 * 4 + 2) * TN + c] = v.z;
                emb_s[(d4 * 4 + 3) * TN + c] = v.w;
            }
            __syncthreads();
            #pragma unroll 4
            for (int kk = 0; kk < TK; kk++) {
                const ulonglong2* ap = reinterpret_cast<const ulonglong2*>(
                    lat_s + (kc + kk) * TM + ty * 8);
                ulonglong2 av0 = ap[0];
                ulonglong2 av1 = ap[1];
                unsigned long long a2[4] = {av0.x, av0.y, av1.x, av1.y};

                const float* bp = emb_s + kk * TN + tx * 8;
                float4 b0 = *reinterpret_cast<const float4*>(bp);
                float4 b1 = *reinterpret_cast<const float4*>(bp + 4);
                unsigned long long bd[8] = {
                    dup2(b0.x), dup2(b0.y), dup2(b0.z), dup2(b0.w),
                    dup2(b1.x), dup2(b1.y), dup2(b1.z), dup2(b1.w)
                };
                #pragma unroll
                for (int i = 0; i < 4; i++)
                    #pragma unroll
                    for (int j = 0; j < 8; j++)
                        ffma2(acc2[i][j], a2[i], bd[j]);
            }
        }

        // Epilogue: reference-faithful dist + running argmin (k ascending per row)
        #pragma unroll
        for (int j = 0; j < 8; j++) {
            int   k  = kc0 + tx * 8 + j;
            float b2 = b2_s[tx * 8 + j];
            #pragma unroll
            for (int i2 = 0; i2 < 4; i2++) {
                float dlo, dhi;
                unpack2(acc2[i2][j], dlo, dhi);
                float d0 = __fsub_rn(__fadd_rn(Areg[2*i2],     b2), __fmul_rn(2.0f, dlo));
                float d1 = __fsub_rn(__fadd_rn(Areg[2*i2 + 1], b2), __fmul_rn(2.0f, dhi));
                if (d0 < minv[2*i2])     { minv[2*i2]     = d0; mini[2*i2]     = k; }
                if (d1 < minv[2*i2 + 1]) { minv[2*i2 + 1] = d1; mini[2*i2 + 1] = k; }
            }
        }
    }

    // Cross-thread reduction over the 16 column-group threads per row
    __syncthreads();
    float* redv = emb_s;                        // [TM][16]
    int*   redi = (int*)(emb_s + TM * 16);      // [TM][16]
    #pragma unroll
    for (int i = 0; i < 8; i++) {
        int r = ty * 8 + i;
        redv[r * 16 + tx] = minv[i];
        redi[r * 16 + tx] = mini[i];
    }
    __syncthreads();
    if (tid < TM) {
        float bv = redv[tid * 16];
        int   bi = redi[tid * 16];
        #pragma unroll
        for (int t = 1; t < 16; t++) {
            float v  = redv[tid * 16 + t];
            int   ii = redi[tid * 16 + t];
            if (v < bv || (v == bv && ii < bi)) { bv = v; bi = ii; }
        }
        g_minval[row0 + tid] = bv;
        g_minidx[row0 + tid] = bi;
    }
}

// ---------------------------------------------------------------------------
__global__ void vq_hist(float* __restrict__ out_inds)
{
    __shared__ float s[256];
    int b = blockIdx.x * blockDim.x + threadIdx.x;
    float v = 0.f;
    if (b < BN) {
        int idx = g_minidx[b];
        out_inds[b] = (float)idx;
        atomicAdd(&g_counts[idx], 1);
        v = g_minval[b];
    }
    s[threadIdx.x] = v;
    __syncthreads();
    for (int o = 128; o > 0; o >>= 1) {
        if (threadIdx.x < o) s[threadIdx.x] += s[threadIdx.x + o];
        __syncthreads();
    }
    if (threadIdx.x == 0) atomicAdd(&g_mindsum, s[0]);
}

// Gather + straight-through output + squared-error sum.
// quantized_st replicated exactly as reference: fl(l + fl(q - l))
__global__ void vq_gather(const float* __restrict__ lat, const float* __restrict__ emb,
                          float* __restrict__ outq)
{
    __shared__ float s[256];
    int i4 = blockIdx.x * blockDim.x + threadIdx.x;
    float ls = 0.f;
    if (i4 < BN * DN / 4) {
        int b   = i4 >> 6;   // / (DN/4)
        int idx = g_minidx[b];
        float4 l = reinterpret_cast<const float4*>(lat)[i4];
        float4 q = reinterpret_cast<const float4*>(emb)[(size_t)idx * (DN / 4) + (i4 & 63)];
        float4 o; float d;
        d = __fsub_rn(q.x, l.x); o.x = __fadd_rn(l.x, d); ls = __fmaf_rn(d, d, ls);
        d = __fsub_rn(q.y, l.y); o.y = __fadd_rn(l.y, d); ls = __fmaf_rn(d, d, ls);
        d = __fsub_rn(q.z, l.z); o.z = __fadd_rn(l.z, d); ls = __fmaf_rn(d, d, ls);
        d = __fsub_rn(q.w, l.w); o.w = __fadd_rn(l.w, d); ls = __fmaf_rn(d, d, ls);
        reinterpret_cast<float4*>(outq)[i4] = o;
    }
    s[threadIdx.x] = ls;
    __syncthreads();
    for (int o2 = 128; o2 > 0; o2 >>= 1) {
        if (threadIdx.x < o2) s[threadIdx.x] += s[threadIdx.x + o2];
        __syncthreads();
    }
    if (threadIdx.x == 0) atomicAdd(&g_sqsum, s[0]);
}

__global__ void vq_finalize(float* __restrict__ out_tail)
{
    __shared__ float s[256];
    float loc = 0.f;
    for (int k = threadIdx.x; k < KN; k += 256) {
        float p = (float)g_counts[k] * (1.0f / BN);
        loc += p * logf(p + 1e-10f);
    }
    s[threadIdx.x] = loc;
    __syncthreads();
    for (int o = 128; o > 0; o >>= 1) {
        if (threadIdx.x < o) s[threadIdx.x] += s[threadIdx.x + o];
        __syncthreads();
    }
    if (threadIdx.x == 0) {
        float mse = g_sqsum * (1.0f / (float)(BN * (size_t)DN));  // 2^-23 exact
        out_tail[0] = __fadd_rn(__fmul_rn(mse, 0.25f), mse);      // beta*c + e
        out_tail[1] = -s[0];                                       // entropy
        out_tail[2 + BN] = g_mindsum * (1.0f / BN);                // cluster metric
    }
}

// ---------------------------------------------------------------------------
extern "C" void kernel_launch(void* const* d_in, const int* in_sizes, int n_in,
                              void* d_out, int out_size)
{
    (void)in_sizes; (void)n_in; (void)out_size;
    const float* lat = (const float*)d_in[0];   // [BN, DN] fp32
    const float* emb = (const float*)d_in[1];   // [KN, DN] fp32
    float* out = (float*)d_out;

    cudaFuncSetAttribute(vq_gemm_argmin,
                         cudaFuncAttributeMaxDynamicSharedMemorySize, SMEM_BYTES);

    vq_init<<<(KN + 255) / 256, 256>>>();
    vq_rowsumsq<<<(BN * 32) / 256, 256>>>(lat, BN, 0);
    vq_rowsumsq<<<(KN * 32) / 256, 256>>>(emb, KN, 1);
    vq_gemm_argmin<<<BN / TM, 256, SMEM_BYTES>>>(lat, emb);
    vq_hist<<<BN / 256, 256>>>(out + IND_OFF);
    vq_gather<<<(BN * DN / 4) / 256, 256>>>(lat, emb, out + Q_OFF);
    vq_finalize<<<1, 256>>>(out + TAIL_OFF);
}